// round 9
// baseline (speedup 1.0000x reference)
#include <cuda_runtime.h>
#include <math.h>

#define RF   1024
#define US   200
#define MGC  60
#define FS   64
#define NS   4
#define NL   10
#define NWIN 1600
#define VSCALE 0.70710678118f

typedef unsigned long long ull;

// Scratch (device globals: no allocation allowed)
__device__ float g_newA[NWIN];
__device__ float g_newB[NWIN];
__device__ float g_cond[NWIN * MGC];
// l=1 weights, transposed:   [s][ob4][k][c][o16] as float2(wx,wy)   = 98304 floats
__device__ float g_wT[98304];
// l=2..7 weights, duplicated: [s][li6][ob2][k][c][o32] as float4(wx,wx,wy,wy) = 1179648 floats
__device__ float g_wdup[1179648];

// ---------------- packed f32x2 helpers ----------------
__device__ __forceinline__ ull ffma2(ull a, ull b, ull c) {
    ull d; asm("fma.rn.f32x2 %0, %1, %2, %3;" : "=l"(d) : "l"(a), "l"(b), "l"(c)); return d;
}
__device__ __forceinline__ float2 unpk(ull v) {
    float2 r; asm("mov.b64 {%0,%1}, %2;" : "=f"(r.x), "=f"(r.y) : "l"(v)); return r;
}
__device__ __forceinline__ ull pk2(float x, float y) {
    ull v; asm("mov.b64 %0, {%1,%2};" : "=l"(v) : "f"(x), "f"(y)); return v;
}

__device__ __forceinline__ float sigmoidf_(float v) { return 1.0f / (1.0f + expf(-v)); }
__device__ __forceinline__ float gatef_(float aI, float aG, float aR) {
    return (tanhf(aI) * sigmoidf_(aG) + aR) * VSCALE;
}

// ---------------- prep kernels ----------------
__global__ void k_wprep(const float* __restrict__ convs_w) {
    int i = blockIdx.x * blockDim.x + threadIdx.x;
    // g_wT: float2 idx = (((s*4+ob)*3+k)*64+c)*16 + o16 ; count 49152
    if (i < 49152) {
        int o16 = i & 15; int r = i >> 4;
        int c = r & 63; r >>= 6;
        int k = r % 3; r /= 3;
        int ob = r & 3; int s = r >> 2;
        int o = ob * 16 + o16;
        const float* w = convs_w + ((((size_t)s * 9 + 0) * 3 + k) * 64 + o) * 128 + c * 2;
        ((float2*)g_wT)[i] = make_float2(w[0], w[1]);
    }
    // g_wdup: float4 idx = ((((s*6+li)*2+ob)*3+k)*64+c)*32 + o32 ; count 294912
    if (i < 294912) {
        int o32 = i & 31; int r = i >> 5;
        int c = r & 63; r >>= 6;
        int k = r % 3; r /= 3;
        int ob = r & 1; r >>= 1;
        int li = r % 6; int s = r / 6;
        int l = li + 2;
        int o = ob * 32 + o32;
        const float* w = convs_w + ((((size_t)s * 9 + (l - 1)) * 3 + k) * 64 + o) * 128 + c * 2;
        ((float4*)g_wdup)[i] = make_float4(w[0], w[0], w[1], w[1]);
    }
}

__global__ void k_cond(const float* __restrict__ mgc,
                       const float* __restrict__ cond_w,
                       const float* __restrict__ cond_b) {
    int n = blockIdx.x;
    int m = threadIdx.x;
    if (m >= MGC) return;
    int f = n / US, u = n % US;
    int r = u * MGC + m;
    const float* wrow = cond_w + (size_t)r * MGC;
    const float* mrow = mgc + f * MGC;
    float acc = cond_b[r];
#pragma unroll
    for (int k = 0; k < MGC; k++) acc += mrow[k] * wrow[k];
    g_cond[n * MGC + m] = tanhf(acc);
}

// ---------------- per-stage kernel: one CTA = one window ----------------
// smem (floats): xwin 1024 | condv 64 | cproj 1280 | wbuf 6144 | buf1 32768 | buf2 16384
// wfull = buf1 + 8192 (24576 floats), used l>=2 when activations are small.
// Activations are stored DE-INTERLEAVED: E (even j) rows then O (odd j) rows.
#define SM_XWIN  0
#define SM_COND  1024
#define SM_CPROJ 1088
#define SM_WBUF  2368
#define SM_BUF1  8512
#define SM_BUF2  41280
#define SM_FLOATS (41280 + 16384)
#define SMEM_BYTES (SM_FLOATS * 4)

// epilogue for one output channel: acc = [Ip0, Ip1, Gp0, Gp1, Rp0, Rp1]
__device__ __forceinline__ void epi_o(
    float* dst, int Hout, int o, int q, int l,
    const float* b, const float* cproj, const ull* acc)
{
    float bI = b[o] + cproj[l * 128 + o];
    float bG = b[64 + o] + cproj[l * 128 + 64 + o];
    float bR = b[128 + o];
    float2 aI0 = unpk(acc[0]), aI1 = unpk(acc[1]);
    float2 aG0 = unpk(acc[2]), aG1 = unpk(acc[3]);
    float2 aR0 = unpk(acc[4]), aR1 = unpk(acc[5]);
    float2 ye = make_float2(gatef_(aI0.x + bI, aG0.x + bG, aR0.x + bR),
                            gatef_(aI1.x + bI, aG1.x + bG, aR1.x + bR));
    float2 yo = make_float2(gatef_(aI0.y + bI, aG0.y + bG, aR0.y + bR),
                            gatef_(aI1.y + bI, aG1.y + bG, aR1.y + bR));
    *(float2*)(dst + o * Hout + 2 * q) = ye;
    *(float2*)(dst + (Hout << 6) + o * Hout + 2 * q) = yo;
}

__global__ __launch_bounds__(512, 1) void k_stage(
    int s,
    const float* __restrict__ noise,
    const float* __restrict__ gin,
    float* __restrict__ gout,
    const float* __restrict__ conv0_w, const float* __restrict__ convs_w,
    const float* __restrict__ conv_b,
    const float* __restrict__ pre_w, const float* __restrict__ pre_b,
    const float* __restrict__ mean_w, const float* __restrict__ mean_b,
    const float* __restrict__ std_w, const float* __restrict__ std_b,
    const float* __restrict__ ccw, const float* __restrict__ ccb,
    float* __restrict__ out)
{
    extern __shared__ float sm[];
    float* xwin  = sm + SM_XWIN;
    float* condv = sm + SM_COND;
    float* cproj = sm + SM_CPROJ;
    float* wbuf  = sm + SM_WBUF;
    float* buf1  = sm + SM_BUF1;
    float* buf2  = sm + SM_BUF2;
    float* wfull = buf1 + 8192;

    const int n   = blockIdx.x;
    const int tid = threadIdx.x;

    // input window
    for (int i = tid; i < RF; i += 512) {
        int idx = n + i;
        xwin[i] = (s == 0 || idx < RF) ? noise[idx] : gin[idx - RF];
    }
    if (tid < MGC) condv[tid] = g_cond[n * MGC + tid];
    __syncthreads();

    // conditioning projections: cproj[l*128 + k*64 + o]
    for (int idx = tid; idx < NL * 2 * FS; idx += 512) {
        int l = idx >> 7;
        int k = (idx >> 6) & 1;
        int o = idx & 63;
        int base = ((s * NL + l) * 2 + k) * FS + o;
        const float* wr = ccw + (size_t)base * MGC;
        float acc = ccb[base];
#pragma unroll
        for (int m = 0; m < MGC; m++) acc += condv[m] * wr[m];
        cproj[idx] = acc;
    }
    for (int i = tid; i < 384; i += 512) wbuf[i] = conv0_w[s * 384 + i];
    __syncthreads();

    // ---- layer 0: C=1, L 1024 -> 512, write de-interleaved into buf1 ----
    {
        const float* b = conv_b + (size_t)(s * NL + 0) * 3 * FS;
        for (int idx = tid; idx < FS * 256; idx += 512) {
            int o = idx >> 8, m = idx & 255;        // outputs j=2m, 2m+1
            float w0i = wbuf[o * 2],       w1i = wbuf[o * 2 + 1];
            float w0g = wbuf[128 + o * 2], w1g = wbuf[128 + o * 2 + 1];
            float w0r = wbuf[256 + o * 2], w1r = wbuf[256 + o * 2 + 1];
            float bI = b[o] + cproj[o], bG = b[64 + o] + cproj[64 + o], bR = b[128 + o];
            float x0 = xwin[4 * m], x1 = xwin[4 * m + 1];
            float x2 = xwin[4 * m + 2], x3 = xwin[4 * m + 3];
            float y0 = gatef_(w0i * x0 + w1i * x1 + bI, w0g * x0 + w1g * x1 + bG, w0r * x0 + w1r * x1 + bR);
            float y1 = gatef_(w0i * x2 + w1i * x3 + bI, w0g * x2 + w1g * x3 + bG, w0r * x2 + w1r * x3 + bR);
            buf1[o * 256 + m] = y0;                 // E
            buf1[16384 + o * 256 + m] = y1;         // O
        }
    }

    // ---- layer 1: Lin=512 -> Lout=256; 4 blocks of 16 o; plain weights + MOV dup ----
    {
        const int Hin = 256, Hout = 128;
        const float* src = buf1;
        float* dst = buf2;
        const float* b = conv_b + (size_t)(s * NL + 1) * 3 * FS;
        const int op = tid >> 6;        // 0..7 (o-pair)
        const int q  = tid & 63;        // j-quad
        for (int ob = 0; ob < 4; ob++) {
            __syncthreads();
            for (int i = tid; i < 1536; i += 512)
                ((float4*)wbuf)[i] = ((const float4*)(g_wT + (size_t)(s * 4 + ob) * 6144))[i];
            __syncthreads();
            ull acc[12];
#pragma unroll
            for (int a = 0; a < 12; a++) acc[a] = 0ULL;
            const float* Ein = src;
            const float* Oin = src + 64 * Hin;
#pragma unroll 2
            for (int c = 0; c < 64; c++) {
                ulonglong2 xe = *(const ulonglong2*)(Ein + c * Hin + 4 * q);
                ulonglong2 xo = *(const ulonglong2*)(Oin + c * Hin + 4 * q);
#pragma unroll
                for (int kk = 0; kk < 3; kk++) {
                    float4 wv = ((const float4*)wbuf)[(kk * 64 + c) * 8 + op];
                    ull A0 = pk2(wv.x, wv.x), A1 = pk2(wv.y, wv.y);
                    ull B0 = pk2(wv.z, wv.z), B1 = pk2(wv.w, wv.w);
                    acc[kk*2+0] = ffma2(A0, xe.x, ffma2(A1, xo.x, acc[kk*2+0]));
                    acc[kk*2+1] = ffma2(A0, xe.y, ffma2(A1, xo.y, acc[kk*2+1]));
                    acc[6+kk*2+0] = ffma2(B0, xe.x, ffma2(B1, xo.x, acc[6+kk*2+0]));
                    acc[6+kk*2+1] = ffma2(B0, xe.y, ffma2(B1, xo.y, acc[6+kk*2+1]));
                }
            }
            epi_o(dst, Hout, ob * 16 + 2 * op,     q, 1, b, cproj, acc);
            epi_o(dst, Hout, ob * 16 + 2 * op + 1, q, 1, b, cproj, acc + 6);
        }
        __syncthreads();
    }

    // ---- layers 2..7: duplicated weights, 2 blocks of 32 o ----
    for (int l = 2; l <= 7; l++) {
        const int Lin  = RF >> l;
        const int Hin  = Lin >> 1;
        const int Hout = Lin >> 2;
        const int qsh  = 7 - l;              // log2(quads)
        const int quads = 1 << qsh;
        const float* src = (l & 1) ? buf1 : buf2;
        float* dst       = (l & 1) ? buf2 : buf1;
        const float* b = conv_b + (size_t)(s * NL + l) * 3 * FS;
        const float* Wd = g_wdup + (size_t)(s * 6 + (l - 2)) * 2 * 24576;
        const int nit = 16 << qsh;
        const int q  = tid & (quads - 1);
        const int op = tid >> qsh;

        for (int ob = 0; ob < 2; ob++) {
            __syncthreads();
            for (int i = tid; i < 6144; i += 512)
                ((float4*)wfull)[i] = ((const float4*)(Wd + ob * 24576))[i];
            __syncthreads();
            if (tid < nit) {
                const ulonglong2* wst = (const ulonglong2*)wfull;
                ull acc[12];
#pragma unroll
                for (int a = 0; a < 12; a++) acc[a] = 0ULL;
                const float* Ein = src;
                const float* Oin = src + 64 * Hin;
#pragma unroll 2
                for (int c = 0; c < 64; c++) {
                    ulonglong2 xe = *(const ulonglong2*)(Ein + c * Hin + 4 * q);
                    ulonglong2 xo = *(const ulonglong2*)(Oin + c * Hin + 4 * q);
                    const ulonglong2* wr = wst + (c << 5) + 2 * op;
#pragma unroll
                    for (int kk = 0; kk < 3; kk++) {
                        ulonglong2 wa = wr[kk * 2048];      // o2=0: (wx,wx),(wy,wy)
                        ulonglong2 wb = wr[kk * 2048 + 1];  // o2=1
                        acc[kk*2+0] = ffma2(wa.x, xe.x, ffma2(wa.y, xo.x, acc[kk*2+0]));
                        acc[kk*2+1] = ffma2(wa.x, xe.y, ffma2(wa.y, xo.y, acc[kk*2+1]));
                        acc[6+kk*2+0] = ffma2(wb.x, xe.x, ffma2(wb.y, xo.x, acc[6+kk*2+0]));
                        acc[6+kk*2+1] = ffma2(wb.x, xe.y, ffma2(wb.y, xo.y, acc[6+kk*2+1]));
                    }
                }
                epi_o(dst, Hout, ob * 32 + 2 * op,     q, l, b, cproj, acc);
                epi_o(dst, Hout, ob * 32 + 2 * op + 1, q, l, b, cproj, acc + 6);
            }
        }
        __syncthreads();
    }

    // ---- layer 8: Lin=4 -> Lout=2 (src=buf2: E=buf2[0..127], O=buf2[128..255]) ----
    {
        const int l = 8;
        const float* Wg = convs_w + (size_t)(s * 9 + (l - 1)) * 3 * FS * FS * 2;
        const float* b  = conv_b + (size_t)(s * NL + l) * 3 * FS;
        __syncthreads();
        {
            const float2* src2 = (const float2*)Wg;
            float2* w2 = (float2*)wfull;
            for (int g = tid; g < 12288; g += 512) {
                int o = (g >> 6) & 63;
                int didx = (g & ~63) | ((g ^ o) & 63);
                w2[didx] = src2[g];
            }
        }
        __syncthreads();
        if (tid < FS) {
            const int o = tid;
            const float2* w2 = (const float2*)wfull;
            const float* E8 = buf2;
            const float* O8 = buf2 + 128;
            float acc[6];
#pragma unroll
            for (int a = 0; a < 6; a++) acc[a] = 0.f;
#pragma unroll 4
            for (int c = 0; c < FS; c++) {
                float e0 = E8[2 * c], e1 = E8[2 * c + 1];
                float o0 = O8[2 * c], o1 = O8[2 * c + 1];
                int cx = c ^ o;
#pragma unroll
                for (int k = 0; k < 3; k++) {
                    float2 wv = w2[(((k << 6) + o) << 6) + cx];
                    acc[k*2+0] = fmaf(wv.x, e0, acc[k*2+0]); acc[k*2+0] = fmaf(wv.y, o0, acc[k*2+0]);
                    acc[k*2+1] = fmaf(wv.x, e1, acc[k*2+1]); acc[k*2+1] = fmaf(wv.y, o1, acc[k*2+1]);
                }
            }
            float bI = b[o] + cproj[l * 128 + o];
            float bG = b[64 + o] + cproj[l * 128 + 64 + o];
            float bR = b[128 + o];
            buf1[o]      = gatef_(acc[0] + bI, acc[2] + bG, acc[4] + bR);  // E (j=0)
            buf1[64 + o] = gatef_(acc[1] + bI, acc[3] + bG, acc[5] + bR);  // O (j=1)
        }
        __syncthreads();
    }

    // ---- layer 9: Lin=2 -> Lout=1 (src: E=buf1[0..63], O=buf1[64..127]) ----
    {
        const int l = 9;
        const float* Wg = convs_w + (size_t)(s * 9 + (l - 1)) * 3 * FS * FS * 2;
        const float* b  = conv_b + (size_t)(s * NL + l) * 3 * FS;
        {
            const float2* src2 = (const float2*)Wg;
            float2* w2 = (float2*)wfull;
            for (int g = tid; g < 12288; g += 512) {
                int o = (g >> 6) & 63;
                int didx = (g & ~63) | ((g ^ o) & 63);
                w2[didx] = src2[g];
            }
        }
        __syncthreads();
        if (tid < FS) {
            const int o = tid;
            const float2* w2 = (const float2*)wfull;
            const float* E9 = buf1;
            const float* O9 = buf1 + 64;
            float a0 = 0.f, a1 = 0.f, a2 = 0.f;
#pragma unroll 8
            for (int c = 0; c < FS; c++) {
                float xe = E9[c], xo = O9[c];
                int cx = c ^ o;
                float2 w0 = w2[((0 * FS + o) << 6) + cx];
                float2 w1 = w2[((1 * FS + o) << 6) + cx];
                float2 w3 = w2[((2 * FS + o) << 6) + cx];
                a0 = fmaf(w0.x, xe, a0); a0 = fmaf(w0.y, xo, a0);
                a1 = fmaf(w1.x, xe, a1); a1 = fmaf(w1.y, xo, a1);
                a2 = fmaf(w3.x, xe, a2); a2 = fmaf(w3.y, xo, a2);
            }
            float bI = b[o] + cproj[l * 128 + o];
            float bG = b[64 + o] + cproj[l * 128 + 64 + o];
            float bR = b[128 + o];
            buf2[o] = gatef_(a0 + bI, a1 + bG, a2 + bR);
        }
        __syncthreads();
    }

    // ---- head ----
    {
        float mpart = 0.f, vpart = 0.f;
        if (tid < 256) {
            const int p = tid;
            const float* pw = pre_w + (size_t)(s * 256 + p) * FS;
            float acc = pre_b[s * 256 + p];
#pragma unroll
            for (int o = 0; o < FS; o++) acc += buf2[o] * pw[o];
            float pre = fmaxf(acc, 0.f);
            mpart = pre * mean_w[s * 256 + p];
            vpart = pre * std_w[s * 256 + p];
        }
        float* red  = wbuf;
        float* red2 = wbuf + 256;
        __syncthreads();
        if (tid < 256) { red[tid] = mpart; red2[tid] = vpart; }
        __syncthreads();
        for (int st = 128; st > 0; st >>= 1) {
            if (tid < st) { red[tid] += red[tid + st]; red2[tid] += red2[tid + st]; }
            __syncthreads();
        }
        if (tid == 0) {
            float mean   = red[0]  + mean_b[s];
            float logvar = red2[0] + std_b[s];
            float eps = (s == 0) ? noise[RF + n] : gin[n];
            float nv = eps * expf(0.5f * logvar) + mean;
            gout[n] = nv;
            if (n >= NWIN - RF)
                out[3 * NWIN + s * RF + (n - (NWIN - RF))] = nv;
            if (s == NS - 1) {
                out[n] = nv;
                out[NWIN + n] = mean;
                out[2 * NWIN + n] = logvar;
            }
        }
    }
}

// ---------------- launcher ----------------
extern "C" void kernel_launch(void* const* d_in, const int* in_sizes, int n_in,
                              void* d_out, int out_size) {
    const float* mgc     = (const float*)d_in[0];
    const float* noise   = (const float*)d_in[1];
    const float* cond_w  = (const float*)d_in[2];
    const float* cond_b  = (const float*)d_in[3];
    const float* conv0_w = (const float*)d_in[4];
    const float* convs_w = (const float*)d_in[5];
    const float* conv_b  = (const float*)d_in[6];
    const float* ccw     = (const float*)d_in[7];
    const float* ccb     = (const float*)d_in[8];
    const float* pre_w   = (const float*)d_in[9];
    const float* pre_b   = (const float*)d_in[10];
    const float* mean_w  = (const float*)d_in[11];
    const float* mean_b  = (const float*)d_in[12];
    const float* std_w   = (const float*)d_in[13];
    const float* std_b   = (const float*)d_in[14];
    float* out = (float*)d_out;

    cudaFuncSetAttribute(k_stage, cudaFuncAttributeMaxDynamicSharedMemorySize, SMEM_BYTES);

    float* nA = nullptr; float* nB = nullptr;
    cudaGetSymbolAddress((void**)&nA, g_newA);
    cudaGetSymbolAddress((void**)&nB, g_newB);

    k_wprep<<<(294912 + 255) / 256, 256>>>(convs_w);
    k_cond<<<NWIN, 64>>>(mgc, cond_w, cond_b);

    for (int s = 0; s < NS; s++) {
        const float* gin = (s & 1) ? nA : nB;   // s=0 ignores gin
        float* gout      = (s & 1) ? nB : nA;
        k_stage<<<NWIN, 512, SMEM_BYTES>>>(s, noise, gin, gout,
                                           conv0_w, convs_w, conv_b,
                                           pre_w, pre_b, mean_w, mean_b,
                                           std_w, std_b, ccw, ccb, out);
    }
}